// round 3
// baseline (speedup 1.0000x reference)
#include <cuda_runtime.h>
#include <cstdint>

// Problem constants
#define BB   2
#define LL   2048
#define HID  2048
#define HH   32
#define KVH  8
#define DD   64
#define NREP (HH / KVH)
#define MM   (BB * LL)          // 4096 rows

// Scratch (device globals; no dynamic allocation allowed).
// g_q doubles as the attention-output buffer (safe: each flash CTA reads only
// its own Q tile into smem before overwriting the identical region).
__device__ float g_q[MM * HH * DD];     // 4096 x 2048 (32 MB)
__device__ float g_k[MM * KVH * DD];    // 4096 x 512  (8 MB)
__device__ float g_v[MM * KVH * DD];    // 4096 x 512  (8 MB)

// ---------------------------------------------------------------------------
// NT SGEMM: C[M,N] = A[M,K] @ B[N,K]^T, all row-major, fp32.
// 128x128 tile, BK=8, 256 threads, 8x8 micro-tile per thread.
// ROPE_HEADD != 0 enables fused RoPE in the epilogue: output column n maps to
// (head = n / ROPE_HEADD_DUMMY ... ) -- we only need pair index within a head:
// pairs are (2i, 2i+1) within each D=64 head slice. Since GBN columns per
// thread are 2x float4 = 8 consecutive columns and DD % 8 == 0, each thread's
// slab is pair-aligned and within one head.
// ---------------------------------------------------------------------------
#define GBM 128
#define GBN 128
#define GBK 8

template <bool ROPE>
__global__ __launch_bounds__(256) void sgemm_nt(const float* __restrict__ A,
                                                const float* __restrict__ B,
                                                float* __restrict__ C,
                                                int M, int N, int K,
                                                const float* __restrict__ fcos,
                                                const float* __restrict__ fsin) {
    __shared__ float As[GBK][GBM];
    __shared__ float Bs[GBK][GBN];

    const int t  = threadIdx.x;
    const int tx = t & 15;       // 0..15
    const int ty = t >> 4;       // 0..15
    const int bm = blockIdx.y * GBM;
    const int bn = blockIdx.x * GBN;

    const int lr = t >> 1;        // 0..127
    const int lc = (t & 1) * 4;   // 0 or 4

    float acc[8][8];
#pragma unroll
    for (int i = 0; i < 8; i++)
#pragma unroll
        for (int j = 0; j < 8; j++) acc[i][j] = 0.f;

    const float* aptr = A + (size_t)(bm + lr) * K + lc;
    const float* bptr = B + (size_t)(bn + lr) * K + lc;

    for (int k0 = 0; k0 < K; k0 += GBK) {
        float4 av = *(const float4*)(aptr + k0);
        float4 bv = *(const float4*)(bptr + k0);
        __syncthreads();
        As[lc + 0][lr] = av.x; As[lc + 1][lr] = av.y;
        As[lc + 2][lr] = av.z; As[lc + 3][lr] = av.w;
        Bs[lc + 0][lr] = bv.x; Bs[lc + 1][lr] = bv.y;
        Bs[lc + 2][lr] = bv.z; Bs[lc + 3][lr] = bv.w;
        __syncthreads();

#pragma unroll
        for (int kk = 0; kk < GBK; kk++) {
            float a[8], b[8];
            *(float4*)(a)     = *(const float4*)&As[kk][ty * 8];
            *(float4*)(a + 4) = *(const float4*)&As[kk][ty * 8 + 4];
            *(float4*)(b)     = *(const float4*)&Bs[kk][tx * 8];
            *(float4*)(b + 4) = *(const float4*)&Bs[kk][tx * 8 + 4];
#pragma unroll
            for (int i = 0; i < 8; i++)
#pragma unroll
                for (int j = 0; j < 8; j++)
                    acc[i][j] = fmaf(a[i], b[j], acc[i][j]);
        }
    }

    if (ROPE) {
        // Output row -> sequence position; column n -> (head, d) with d = n % DD.
        // Each thread owns 8 consecutive columns starting at cn0 = bn + tx*8.
        // Pairs: (d0+2j, d0+2j+1), pair index i_p = (d0+2j)/2.
        const int cn0 = bn + tx * 8;
        const int d0  = cn0 % DD;          // 0..56, multiple of 8
#pragma unroll
        for (int i = 0; i < 8; i++) {
            int row = bm + ty * 8 + i;
            int l   = row % LL;            // sequence position
#pragma unroll
            for (int j = 0; j < 4; j++) {
                int ip = (d0 >> 1) + j;    // pair index within head (0..31)
                float c = fcos[l * (DD / 2) + ip];
                float s = fsin[l * (DD / 2) + ip];
                float x1 = acc[i][2 * j];
                float x2 = acc[i][2 * j + 1];
                acc[i][2 * j]     = x1 * c - x2 * s;
                acc[i][2 * j + 1] = x1 * s + x2 * c;
            }
        }
    }

#pragma unroll
    for (int i = 0; i < 8; i++) {
        float* cp = C + (size_t)(bm + ty * 8 + i) * N + bn + tx * 8;
        *(float4*)(cp)     = *(const float4*)&acc[i][0];
        *(float4*)(cp + 4) = *(const float4*)&acc[i][4];
    }
}

// ---------------------------------------------------------------------------
// Flash-style causal attention, fp32.
// CTA = (qblock of 64, head, batch). 256 threads, 4x4 fragments.
// Smem: Qs (transposed [d][r], stride 65), Ks (transposed [d][c], stride 65,
// reused as Ps[c][r]), Vs (natural [c][d], stride 64).
// Online softmax with half-warp butterfly reductions.
// Output o may alias q (per-CTA region identical, Q consumed to smem first).
// ---------------------------------------------------------------------------
#define FBQ 64
#define FBK 64
#define TSTRIDE 65

__global__ __launch_bounds__(256) void flash_kernel(const float* __restrict__ q,
                                                    const float* __restrict__ k,
                                                    const float* __restrict__ v,
                                                    float* __restrict__ o) {
    extern __shared__ float sm[];
    float* Qs = sm;                    // 64*65
    float* Ks = sm + FBQ * TSTRIDE;    // 64*65 (reused for P)
    float* Vs = Ks + FBK * TSTRIDE;    // 64*64

    const int t  = threadIdx.x;
    const int tx = t & 15;
    const int ty = t >> 4;
    const int qb = (int)gridDim.x - 1 - (int)blockIdx.x;   // longest first
    const int h  = blockIdx.y;
    const int b  = blockIdx.z;
    const int q0 = qb * FBQ;
    const int kvh = h / NREP;

    const float* qptr = q + (size_t)(b * LL + q0) * (HH * DD) + h * DD;
    const float* kbase = k + (size_t)(b * LL) * (KVH * DD) + kvh * DD;
    const float* vbase = v + (size_t)(b * LL) * (KVH * DD) + kvh * DD;

    // Load Q tile transposed: Qs[d][r]
#pragma unroll
    for (int it = 0; it < 4; it++) {
        int idx = t + 256 * it;         // 0..1023
        int r   = idx >> 4;             // 0..63
        int d4  = (idx & 15) * 4;
        float4 vq = *(const float4*)(qptr + (size_t)r * (HH * DD) + d4);
        Qs[(d4 + 0) * TSTRIDE + r] = vq.x;
        Qs[(d4 + 1) * TSTRIDE + r] = vq.y;
        Qs[(d4 + 2) * TSTRIDE + r] = vq.z;
        Qs[(d4 + 3) * TSTRIDE + r] = vq.w;
    }

    float m_i[4], l_i[4], o_f[4][4];
#pragma unroll
    for (int i = 0; i < 4; i++) {
        m_i[i] = -1e30f;
        l_i[i] = 0.f;
#pragma unroll
        for (int j = 0; j < 4; j++) o_f[i][j] = 0.f;
    }

    for (int j0 = 0; j0 <= qb; j0++) {
        const int kb = j0 * FBK;
        const bool diag = (j0 == qb);
        __syncthreads();   // previous P/V reads done before overwriting tiles

        // Load K transposed (Ks[d][c]) and V natural (Vs[c][d])
#pragma unroll
        for (int it = 0; it < 4; it++) {
            int idx = t + 256 * it;
            int r   = idx >> 4;
            int d4  = (idx & 15) * 4;
            float4 kv = *(const float4*)(kbase + (size_t)(kb + r) * (KVH * DD) + d4);
            Ks[(d4 + 0) * TSTRIDE + r] = kv.x;
            Ks[(d4 + 1) * TSTRIDE + r] = kv.y;
            Ks[(d4 + 2) * TSTRIDE + r] = kv.z;
            Ks[(d4 + 3) * TSTRIDE + r] = kv.w;
            float4 vv = *(const float4*)(vbase + (size_t)(kb + r) * (KVH * DD) + d4);
            *(float4*)&Vs[r * 64 + d4] = vv;
        }
        __syncthreads();

        // S = Q @ K^T  (4x4 per thread)
        float sfr[4][4];
#pragma unroll
        for (int i = 0; i < 4; i++)
#pragma unroll
            for (int j = 0; j < 4; j++) sfr[i][j] = 0.f;

#pragma unroll 8
        for (int kk = 0; kk < DD; kk++) {
            float a0 = Qs[kk * TSTRIDE + ty * 4 + 0];
            float a1 = Qs[kk * TSTRIDE + ty * 4 + 1];
            float a2 = Qs[kk * TSTRIDE + ty * 4 + 2];
            float a3 = Qs[kk * TSTRIDE + ty * 4 + 3];
            float b0 = Ks[kk * TSTRIDE + tx * 4 + 0];
            float b1 = Ks[kk * TSTRIDE + tx * 4 + 1];
            float b2 = Ks[kk * TSTRIDE + tx * 4 + 2];
            float b3 = Ks[kk * TSTRIDE + tx * 4 + 3];
            sfr[0][0] = fmaf(a0, b0, sfr[0][0]); sfr[0][1] = fmaf(a0, b1, sfr[0][1]);
            sfr[0][2] = fmaf(a0, b2, sfr[0][2]); sfr[0][3] = fmaf(a0, b3, sfr[0][3]);
            sfr[1][0] = fmaf(a1, b0, sfr[1][0]); sfr[1][1] = fmaf(a1, b1, sfr[1][1]);
            sfr[1][2] = fmaf(a1, b2, sfr[1][2]); sfr[1][3] = fmaf(a1, b3, sfr[1][3]);
            sfr[2][0] = fmaf(a2, b0, sfr[2][0]); sfr[2][1] = fmaf(a2, b1, sfr[2][1]);
            sfr[2][2] = fmaf(a2, b2, sfr[2][2]); sfr[2][3] = fmaf(a2, b3, sfr[2][3]);
            sfr[3][0] = fmaf(a3, b0, sfr[3][0]); sfr[3][1] = fmaf(a3, b1, sfr[3][1]);
            sfr[3][2] = fmaf(a3, b2, sfr[3][2]); sfr[3][3] = fmaf(a3, b3, sfr[3][3]);
        }

        // scale + causal mask (matches reference: -1e9 additive mask).
        if (diag) {
#pragma unroll
            for (int i = 0; i < 4; i++) {
                int gr = q0 + ty * 4 + i;
#pragma unroll
                for (int j = 0; j < 4; j++) {
                    int gc = kb + tx * 4 + j;
                    sfr[i][j] = sfr[i][j] * 0.125f + (gc > gr ? -1e9f : 0.f);
                }
            }
        } else {
#pragma unroll
            for (int i = 0; i < 4; i++)
#pragma unroll
                for (int j = 0; j < 4; j++)
                    sfr[i][j] *= 0.125f;
        }

        __syncthreads();  // everyone done reading Ks as K

        // Online softmax per row (replicated across the 16 lanes of a row group)
        float pfr[4][4];
#pragma unroll
        for (int i = 0; i < 4; i++) {
            float mloc = fmaxf(fmaxf(sfr[i][0], sfr[i][1]), fmaxf(sfr[i][2], sfr[i][3]));
#pragma unroll
            for (int off = 1; off < 16; off <<= 1)
                mloc = fmaxf(mloc, __shfl_xor_sync(0xffffffffu, mloc, off));
            float mnew = fmaxf(m_i[i], mloc);
            float alpha = __expf(m_i[i] - mnew);
            float psum = 0.f;
#pragma unroll
            for (int j = 0; j < 4; j++) {
                float p = __expf(sfr[i][j] - mnew);
                pfr[i][j] = p;
                psum += p;
            }
#pragma unroll
            for (int off = 1; off < 16; off <<= 1)
                psum += __shfl_xor_sync(0xffffffffu, psum, off);
            l_i[i] = l_i[i] * alpha + psum;
            m_i[i] = mnew;
#pragma unroll
            for (int j = 0; j < 4; j++) o_f[i][j] *= alpha;
        }

        // Write P into Ks buffer as Ps[c][r]
#pragma unroll
        for (int j = 0; j < 4; j++)
#pragma unroll
            for (int i = 0; i < 4; i++)
                Ks[(tx * 4 + j) * TSTRIDE + (ty * 4 + i)] = pfr[i][j];
        __syncthreads();

        // O += P @ V
#pragma unroll 8
        for (int kk = 0; kk < FBK; kk++) {
            float p0 = Ks[kk * TSTRIDE + ty * 4 + 0];
            float p1 = Ks[kk * TSTRIDE + ty * 4 + 1];
            float p2 = Ks[kk * TSTRIDE + ty * 4 + 2];
            float p3 = Ks[kk * TSTRIDE + ty * 4 + 3];
            float v0 = Vs[kk * 64 + tx * 4 + 0];
            float v1 = Vs[kk * 64 + tx * 4 + 1];
            float v2 = Vs[kk * 64 + tx * 4 + 2];
            float v3 = Vs[kk * 64 + tx * 4 + 3];
            o_f[0][0] = fmaf(p0, v0, o_f[0][0]); o_f[0][1] = fmaf(p0, v1, o_f[0][1]);
            o_f[0][2] = fmaf(p0, v2, o_f[0][2]); o_f[0][3] = fmaf(p0, v3, o_f[0][3]);
            o_f[1][0] = fmaf(p1, v0, o_f[1][0]); o_f[1][1] = fmaf(p1, v1, o_f[1][1]);
            o_f[1][2] = fmaf(p1, v2, o_f[1][2]); o_f[1][3] = fmaf(p1, v3, o_f[1][3]);
            o_f[2][0] = fmaf(p2, v0, o_f[2][0]); o_f[2][1] = fmaf(p2, v1, o_f[2][1]);
            o_f[2][2] = fmaf(p2, v2, o_f[2][2]); o_f[2][3] = fmaf(p2, v3, o_f[2][3]);
            o_f[3][0] = fmaf(p3, v0, o_f[3][0]); o_f[3][1] = fmaf(p3, v1, o_f[3][1]);
            o_f[3][2] = fmaf(p3, v2, o_f[3][2]); o_f[3][3] = fmaf(p3, v3, o_f[3][3]);
        }
    }

    // Epilogue: normalize and store to [B, L, H*D] (may alias q's region)
    float* optr = o + (size_t)(b * LL + q0) * (HH * DD) + h * DD;
#pragma unroll
    for (int i = 0; i < 4; i++) {
        float inv = 1.f / l_i[i];
#pragma unroll
        for (int j = 0; j < 4; j++)
            optr[(size_t)(ty * 4 + i) * (HH * DD) + tx * 4 + j] = o_f[i][j] * inv;
    }
}

// ---------------------------------------------------------------------------
// Launch
// Inputs: 0:x 1:wq 2:wk 3:wv 4:wo 5:freqs_cos 6:freqs_sin 7:mask 8:start_pos
// ---------------------------------------------------------------------------
extern "C" void kernel_launch(void* const* d_in, const int* in_sizes, int n_in,
                              void* d_out, int out_size) {
    const float* x    = (const float*)d_in[0];
    const float* wq   = (const float*)d_in[1];
    const float* wk   = (const float*)d_in[2];
    const float* wv   = (const float*)d_in[3];
    const float* wo   = (const float*)d_in[4];
    const float* fcos = (const float*)d_in[5];
    const float* fsin = (const float*)d_in[6];
    float* out = (float*)d_out;

    float *gq, *gk, *gv;
    cudaGetSymbolAddress((void**)&gq, g_q);
    cudaGetSymbolAddress((void**)&gk, g_k);
    cudaGetSymbolAddress((void**)&gv, g_v);

    // QKV projections (RoPE fused into Q and K epilogues)
    {
        dim3 g(HH * DD / GBN, MM / GBM);
        sgemm_nt<true><<<g, 256>>>(x, wq, gq, MM, HH * DD, HID, fcos, fsin);
    }
    {
        dim3 g(KVH * DD / GBN, MM / GBM);
        sgemm_nt<true ><<<g, 256>>>(x, wk, gk, MM, KVH * DD, HID, fcos, fsin);
        sgemm_nt<false><<<g, 256>>>(x, wv, gv, MM, KVH * DD, HID, nullptr, nullptr);
    }

    // Attention (output written in place over g_q)
    {
        dim3 g(LL / FBQ, HH, BB);
        size_t smem = (2 * FBQ * TSTRIDE + FBK * 64) * sizeof(float); // 49,664 B
        cudaFuncSetAttribute(flash_kernel, cudaFuncAttributeMaxDynamicSharedMemorySize,
                             (int)smem);
        flash_kernel<<<g, 256, smem>>>(gq, gk, gv, gq);
    }

    // Output projection
    {
        dim3 g(HID / GBN, MM / GBM);
        sgemm_nt<false><<<g, 256>>>(gq, wo, out, MM, HID, HH * DD, nullptr, nullptr);
    }
}

// round 5
// speedup vs baseline: 3.0336x; 3.0336x over previous
#include <cuda_runtime.h>
#include <cstdint>

// Problem constants
#define BB   2
#define LL   2048
#define HID  2048
#define HH   32
#define KVH  8
#define DD   64
#define NREP (HH / KVH)
#define MM   (BB * LL)          // 4096 rows

// Scratch (device globals). g_q doubles as attention output (each flash CTA's
// output region == its own Q region, consumed into smem before overwrite).
__device__ float g_q[MM * HH * DD];     // 32 MB
__device__ float g_k[MM * KVH * DD];    // 8 MB
__device__ float g_v[MM * KVH * DD];    // 8 MB

// ---------------------------------------------------------------------------
// TF32 helpers
// ---------------------------------------------------------------------------
__device__ __forceinline__ uint32_t f2tf32(float f) {
    uint32_t r;
    asm("cvt.rna.tf32.f32 %0, %1;" : "=r"(r) : "f"(f));
    return r;
}

__device__ __forceinline__ void mma_tf32(float* c, const uint32_t* a, const uint32_t* b) {
    asm volatile(
        "mma.sync.aligned.m16n8k8.row.col.f32.tf32.tf32.f32 "
        "{%0,%1,%2,%3}, {%4,%5,%6,%7}, {%8,%9}, {%0,%1,%2,%3};"
        : "+f"(c[0]), "+f"(c[1]), "+f"(c[2]), "+f"(c[3])
        : "r"(a[0]), "r"(a[1]), "r"(a[2]), "r"(a[3]), "r"(b[0]), "r"(b[1]));
}

// ---------------------------------------------------------------------------
// TF32 NT GEMM: C[M,N] = A[M,K] @ B[N,K]^T (row-major), fp32 in/out.
// 128x128x16 CTA tile, 256 threads (8 warps), warp tile 32x64 (m16n8k8).
// Optional fused RoPE on the epilogue (pairs = adjacent output columns).
// ---------------------------------------------------------------------------
#define TBM 128
#define TBN 128
#define TBK 16
#define AST 20   // smem stride (16 + 4 pad): conflict-free fragment gathers

template <bool ROPE>
__global__ __launch_bounds__(256) void gemm_tf32(const float* __restrict__ A,
                                                 const float* __restrict__ B,
                                                 float* __restrict__ C,
                                                 int M, int N, int K,
                                                 const float* __restrict__ fcos,
                                                 const float* __restrict__ fsin) {
    __shared__ uint32_t As[TBM * AST];
    __shared__ uint32_t Bs[TBN * AST];

    const int tid  = threadIdx.x;
    const int lane = tid & 31;
    const int wid  = tid >> 5;
    const int g    = lane >> 2;     // 0..7
    const int q    = lane & 3;      // 0..3
    const int wm   = (wid & 3) * 32;
    const int wn   = (wid >> 2) * 64;
    const int bm   = blockIdx.y * TBM;
    const int bn   = blockIdx.x * TBN;

    float acc[2][8][4];
#pragma unroll
    for (int i = 0; i < 2; i++)
#pragma unroll
        for (int j = 0; j < 8; j++)
#pragma unroll
            for (int r = 0; r < 4; r++) acc[i][j][r] = 0.f;

    const int lr = tid >> 2;          // 0..63
    const int lc = (tid & 3) * 4;     // 0,4,8,12
    const float* aG = A + (size_t)(bm + lr) * K + lc;
    const float* bG = B + (size_t)(bn + lr) * K + lc;

    float4 pa0 = *(const float4*)(aG);
    float4 pa1 = *(const float4*)(aG + (size_t)64 * K);
    float4 pb0 = *(const float4*)(bG);
    float4 pb1 = *(const float4*)(bG + (size_t)64 * K);

    for (int k0 = 0; k0 < K; k0 += TBK) {
        // stage (fp32 -> tf32 once)
        {
            uint4 t;
            t.x = f2tf32(pa0.x); t.y = f2tf32(pa0.y); t.z = f2tf32(pa0.z); t.w = f2tf32(pa0.w);
            *(uint4*)&As[lr * AST + lc] = t;
            t.x = f2tf32(pa1.x); t.y = f2tf32(pa1.y); t.z = f2tf32(pa1.z); t.w = f2tf32(pa1.w);
            *(uint4*)&As[(lr + 64) * AST + lc] = t;
            t.x = f2tf32(pb0.x); t.y = f2tf32(pb0.y); t.z = f2tf32(pb0.z); t.w = f2tf32(pb0.w);
            *(uint4*)&Bs[lr * AST + lc] = t;
            t.x = f2tf32(pb1.x); t.y = f2tf32(pb1.y); t.z = f2tf32(pb1.z); t.w = f2tf32(pb1.w);
            *(uint4*)&Bs[(lr + 64) * AST + lc] = t;
        }
        __syncthreads();

        if (k0 + TBK < K) {
            pa0 = *(const float4*)(aG + k0 + TBK);
            pa1 = *(const float4*)(aG + (size_t)64 * K + k0 + TBK);
            pb0 = *(const float4*)(bG + k0 + TBK);
            pb1 = *(const float4*)(bG + (size_t)64 * K + k0 + TBK);
        }

#pragma unroll
        for (int ks = 0; ks < TBK; ks += 8) {
            uint32_t afr[2][4], bfr[8][2];
#pragma unroll
            for (int i = 0; i < 2; i++) {
                int r0 = wm + i * 16 + g;
                afr[i][0] = As[r0 * AST + ks + q];
                afr[i][1] = As[(r0 + 8) * AST + ks + q];
                afr[i][2] = As[r0 * AST + ks + q + 4];
                afr[i][3] = As[(r0 + 8) * AST + ks + q + 4];
            }
#pragma unroll
            for (int j = 0; j < 8; j++) {
                int n0 = wn + j * 8 + g;
                bfr[j][0] = Bs[n0 * AST + ks + q];
                bfr[j][1] = Bs[n0 * AST + ks + q + 4];
            }
#pragma unroll
            for (int i = 0; i < 2; i++)
#pragma unroll
                for (int j = 0; j < 8; j++)
                    mma_tf32(acc[i][j], afr[i], bfr[j]);
        }
        __syncthreads();
    }

    // Epilogue (optional RoPE: c0/c1 and c2/c3 are adjacent-column pairs)
#pragma unroll
    for (int i = 0; i < 2; i++) {
        int r0 = bm + wm + i * 16 + g;
#pragma unroll
        for (int j = 0; j < 8; j++) {
            int cb = bn + wn + j * 8 + 2 * q;
            float c0 = acc[i][j][0], c1 = acc[i][j][1];
            float c2 = acc[i][j][2], c3 = acc[i][j][3];
            if (ROPE) {
                int ip = (cb & (DD - 1)) >> 1;       // pair index within head
                int l0 = r0 & (LL - 1);
                int l1 = (r0 + 8) & (LL - 1);
                float cA = fcos[l0 * (DD / 2) + ip], sA = fsin[l0 * (DD / 2) + ip];
                float cB = fcos[l1 * (DD / 2) + ip], sB = fsin[l1 * (DD / 2) + ip];
                float t0 = c0 * cA - c1 * sA; c1 = c0 * sA + c1 * cA; c0 = t0;
                float t2 = c2 * cB - c3 * sB; c3 = c2 * sB + c3 * cB; c2 = t2;
            }
            float2 v0 = make_float2(c0, c1);
            float2 v1 = make_float2(c2, c3);
            *(float2*)&C[(size_t)r0 * N + cb]       = v0;
            *(float2*)&C[(size_t)(r0 + 8) * N + cb] = v1;
        }
    }
}

// ---------------------------------------------------------------------------
// TF32 flash attention, causal. CTA = (128-query tile, head, batch),
// 256 threads (8 warps, 16 query rows each). KV tiles of 64.
// QK^T and PV via m16n8k8 tf32; P restaged through smem.
// ---------------------------------------------------------------------------
#define FQ  128
#define FK  64
#define QST 68   // stride for Q/K/P smem (68 % 32 == 4 -> conflict-free frags)
#define VST 72   // stride for V smem    (72 % 32 == 8 -> conflict-free frags)

#define SM_Q 0
#define SM_K (FQ * QST)
#define SM_V (SM_K + FK * QST)
#define SM_P (SM_V + FK * VST)
#define SM_TOT_WORDS (SM_P + FQ * QST)

__global__ __launch_bounds__(256) void flash_tf32(const float* q,
                                                  const float* k,
                                                  const float* v,
                                                  float* o) {
    extern __shared__ uint32_t sm[];
    uint32_t* Qs = sm + SM_Q;
    uint32_t* Ks = sm + SM_K;
    uint32_t* Vs = sm + SM_V;
    uint32_t* Ps = sm + SM_P;

    const int tid  = threadIdx.x;
    const int lane = tid & 31;
    const int wid  = tid >> 5;
    const int g    = lane >> 2;
    const int qd   = lane & 3;
    const int wm   = wid * 16;

    const int qb = (int)gridDim.x - 1 - (int)blockIdx.x;   // longest first
    const int h  = blockIdx.y;
    const int b  = blockIdx.z;
    const int q0 = qb * FQ;
    const int kvh = h / NREP;

    const float* qptr  = q + ((size_t)(b * LL + q0)) * (HH * DD) + h * DD;
    const float* kbase = k + ((size_t)(b * LL)) * (KVH * DD) + kvh * DD;
    const float* vbase = v + ((size_t)(b * LL)) * (KVH * DD) + kvh * DD;

    // Load Q tile -> smem (tf32), 128 rows x 64 cols
#pragma unroll
    for (int p = 0; p < 8; p++) {
        int t2  = p * 256 + tid;
        int row = t2 >> 4;
        int c4  = (t2 & 15) * 4;
        float4 vq = *(const float4*)(qptr + (size_t)row * (HH * DD) + c4);
        uint4 t;
        t.x = f2tf32(vq.x); t.y = f2tf32(vq.y); t.z = f2tf32(vq.z); t.w = f2tf32(vq.w);
        *(uint4*)&Qs[row * QST + c4] = t;
    }

    float m_i[2], l_i[2], o_f[8][4];
    m_i[0] = m_i[1] = -1e30f;
    l_i[0] = l_i[1] = 0.f;
#pragma unroll
    for (int j = 0; j < 8; j++)
#pragma unroll
        for (int r = 0; r < 4; r++) o_f[j][r] = 0.f;

    const int gr0 = q0 + wm + g;       // first of this thread's two rows
    const int nkv = (q0 + FQ) / FK;

    for (int j0 = 0; j0 < nkv; j0++) {
        const int kb = j0 * FK;
        const bool needmask = (kb + FK > q0);
        __syncthreads();   // prior PV reads of Vs/Ps complete

        // Load K (rows=kv, stride QST) and V (rows=kv, stride VST)
#pragma unroll
        for (int p = 0; p < 4; p++) {
            int t2  = p * 256 + tid;
            int row = t2 >> 4;
            int c4  = (t2 & 15) * 4;
            float4 kv4 = *(const float4*)(kbase + (size_t)(kb + row) * (KVH * DD) + c4);
            uint4 t;
            t.x = f2tf32(kv4.x); t.y = f2tf32(kv4.y); t.z = f2tf32(kv4.z); t.w = f2tf32(kv4.w);
            *(uint4*)&Ks[row * QST + c4] = t;
            float4 vv4 = *(const float4*)(vbase + (size_t)(kb + row) * (KVH * DD) + c4);
            t.x = f2tf32(vv4.x); t.y = f2tf32(vv4.y); t.z = f2tf32(vv4.z); t.w = f2tf32(vv4.w);
            *(uint4*)&Vs[row * VST + c4] = t;
        }
        __syncthreads();

        // S = Q @ K^T : warp computes 16 rows x 64 cols
        float s[8][4];
#pragma unroll
        for (int j = 0; j < 8; j++)
#pragma unroll
            for (int r = 0; r < 4; r++) s[j][r] = 0.f;

#pragma unroll
        for (int ks = 0; ks < DD; ks += 8) {
            uint32_t afr[4], bfr[8][2];
            int r0 = wm + g;
            afr[0] = Qs[r0 * QST + ks + qd];
            afr[1] = Qs[(r0 + 8) * QST + ks + qd];
            afr[2] = Qs[r0 * QST + ks + qd + 4];
            afr[3] = Qs[(r0 + 8) * QST + ks + qd + 4];
#pragma unroll
            for (int j = 0; j < 8; j++) {
                int n0 = j * 8 + g;
                bfr[j][0] = Ks[n0 * QST + ks + qd];
                bfr[j][1] = Ks[n0 * QST + ks + qd + 4];
            }
#pragma unroll
            for (int j = 0; j < 8; j++) mma_tf32(s[j], afr, bfr[j]);
        }

        // scale + causal mask
        if (needmask) {
#pragma unroll
            for (int j = 0; j < 8; j++) {
                int gc = kb + j * 8 + 2 * qd;
                s[j][0] = s[j][0] * 0.125f + ((gc     > gr0)     ? -1e9f : 0.f);
                s[j][1] = s[j][1] * 0.125f + ((gc + 1 > gr0)     ? -1e9f : 0.f);
                s[j][2] = s[j][2] * 0.125f + ((gc     > gr0 + 8) ? -1e9f : 0.f);
                s[j][3] = s[j][3] * 0.125f + ((gc + 1 > gr0 + 8) ? -1e9f : 0.f);
            }
        } else {
#pragma unroll
            for (int j = 0; j < 8; j++)
#pragma unroll
                for (int r = 0; r < 4; r++) s[j][r] *= 0.125f;
        }

        // Online softmax: this thread owns rows gr0 (regs 0,1) and gr0+8 (2,3).
        // Row spread across quad lanes (xor 1,2).
        {
            float mx0 = -1e30f, mx1 = -1e30f;
#pragma unroll
            for (int j = 0; j < 8; j++) {
                mx0 = fmaxf(mx0, fmaxf(s[j][0], s[j][1]));
                mx1 = fmaxf(mx1, fmaxf(s[j][2], s[j][3]));
            }
            mx0 = fmaxf(mx0, __shfl_xor_sync(0xffffffffu, mx0, 1));
            mx0 = fmaxf(mx0, __shfl_xor_sync(0xffffffffu, mx0, 2));
            mx1 = fmaxf(mx1, __shfl_xor_sync(0xffffffffu, mx1, 1));
            mx1 = fmaxf(mx1, __shfl_xor_sync(0xffffffffu, mx1, 2));

            float mn0 = fmaxf(m_i[0], mx0);
            float mn1 = fmaxf(m_i[1], mx1);
            float al0 = __expf(m_i[0] - mn0);
            float al1 = __expf(m_i[1] - mn1);
            m_i[0] = mn0; m_i[1] = mn1;

            float sum0 = 0.f, sum1 = 0.f;
#pragma unroll
            for (int j = 0; j < 8; j++) {
                float p0 = __expf(s[j][0] - mn0); s[j][0] = p0; sum0 += p0;
                float p1 = __expf(s[j][1] - mn0); s[j][1] = p1; sum0 += p1;
                float p2 = __expf(s[j][2] - mn1); s[j][2] = p2; sum1 += p2;
                float p3 = __expf(s[j][3] - mn1); s[j][3] = p3; sum1 += p3;
            }
            sum0 += __shfl_xor_sync(0xffffffffu, sum0, 1);
            sum0 += __shfl_xor_sync(0xffffffffu, sum0, 2);
            sum1 += __shfl_xor_sync(0xffffffffu, sum1, 1);
            sum1 += __shfl_xor_sync(0xffffffffu, sum1, 2);
            l_i[0] = l_i[0] * al0 + sum0;
            l_i[1] = l_i[1] * al1 + sum1;

#pragma unroll
            for (int j = 0; j < 8; j++) {
                o_f[j][0] *= al0; o_f[j][1] *= al0;
                o_f[j][2] *= al1; o_f[j][3] *= al1;
            }
        }

        // Stage P (tf32) into smem for the PV mma
#pragma unroll
        for (int j = 0; j < 8; j++) {
            int col = j * 8 + 2 * qd;
            uint2 t0, t1;
            t0.x = f2tf32(s[j][0]); t0.y = f2tf32(s[j][1]);
            t1.x = f2tf32(s[j][2]); t1.y = f2tf32(s[j][3]);
            *(uint2*)&Ps[(wm + g) * QST + col]     = t0;
            *(uint2*)&Ps[(wm + g + 8) * QST + col] = t1;
        }
        __syncthreads();

        // O += P @ V
#pragma unroll
        for (int ks = 0; ks < FK; ks += 8) {
            uint32_t afr[4], bfr[8][2];
            int r0 = wm + g;
            afr[0] = Ps[r0 * QST + ks + qd];
            afr[1] = Ps[(r0 + 8) * QST + ks + qd];
            afr[2] = Ps[r0 * QST + ks + qd + 4];
            afr[3] = Ps[(r0 + 8) * QST + ks + qd + 4];
#pragma unroll
            for (int j = 0; j < 8; j++) {
                int n0 = j * 8 + g;
                bfr[j][0] = Vs[(ks + qd) * VST + n0];
                bfr[j][1] = Vs[(ks + qd + 4) * VST + n0];
            }
#pragma unroll
            for (int j = 0; j < 8; j++) mma_tf32(o_f[j], afr, bfr[j]);
        }
    }

    // Epilogue: normalize + store (o may alias q's region for this CTA)
    float inv0 = 1.f / l_i[0];
    float inv1 = 1.f / l_i[1];
    float* obase = o + ((size_t)(b * LL + gr0)) * (HH * DD) + h * DD;
#pragma unroll
    for (int j = 0; j < 8; j++) {
        int col = j * 8 + 2 * qd;
        float2 r0v = make_float2(o_f[j][0] * inv0, o_f[j][1] * inv0);
        float2 r1v = make_float2(o_f[j][2] * inv1, o_f[j][3] * inv1);
        *(float2*)&obase[col] = r0v;
        *(float2*)&obase[(size_t)8 * (HH * DD) + col] = r1v;
    }
}

// ---------------------------------------------------------------------------
// Launch
// Inputs: 0:x 1:wq 2:wk 3:wv 4:wo 5:freqs_cos 6:freqs_sin 7:mask 8:start_pos
// ---------------------------------------------------------------------------
extern "C" void kernel_launch(void* const* d_in, const int* in_sizes, int n_in,
                              void* d_out, int out_size) {
    const float* x    = (const float*)d_in[0];
    const float* wq   = (const float*)d_in[1];
    const float* wk   = (const float*)d_in[2];
    const float* wv   = (const float*)d_in[3];
    const float* wo   = (const float*)d_in[4];
    const float* fcos = (const float*)d_in[5];
    const float* fsin = (const float*)d_in[6];
    float* out = (float*)d_out;

    float *gq, *gk, *gv;
    cudaGetSymbolAddress((void**)&gq, g_q);
    cudaGetSymbolAddress((void**)&gk, g_k);
    cudaGetSymbolAddress((void**)&gv, g_v);

    // QKV projections (RoPE fused into Q and K epilogues)
    {
        dim3 g(HH * DD / TBN, MM / TBM);
        gemm_tf32<true><<<g, 256>>>(x, wq, gq, MM, HH * DD, HID, fcos, fsin);
    }
    {
        dim3 g(KVH * DD / TBN, MM / TBM);
        gemm_tf32<true ><<<g, 256>>>(x, wk, gk, MM, KVH * DD, HID, fcos, fsin);
        gemm_tf32<false><<<g, 256>>>(x, wv, gv, MM, KVH * DD, HID, nullptr, nullptr);
    }

    // Attention (output written in place over g_q)
    {
        dim3 g(LL / FQ, HH, BB);
        int smem = SM_TOT_WORDS * 4;   // 105,472 B
        cudaFuncSetAttribute(flash_tf32, cudaFuncAttributeMaxDynamicSharedMemorySize, smem);
        flash_tf32<<<g, 256, smem>>>(gq, gk, gv, gq);
    }

    // Output projection
    {
        dim3 g(HID / TBN, MM / TBM);
        gemm_tf32<false><<<g, 256>>>(gq, wo, out, MM, HID, HH * DD, nullptr, nullptr);
    }
}